// round 1
// baseline (speedup 1.0000x reference)
#include <cuda_runtime.h>
#include <math.h>

// Problem constants
// B=8, L=4096, D=1024, H=16, T=64, hd=64

// Scratch arena layout (floats):
//   [0,        33554432)  K proj   [32768,1024]     (reused as H [32768,2048] later)
//   [33554432, 67108864)  V proj   [32768,1024]
//   [67108864, 67174400)  Q proj   [64,1024]
//   [67174400, 67698688)  attn out [512,1024]
//   [67698688, 68222976)  out-proj [512,1024]
__device__ float g_scratch[68222976];

__device__ __forceinline__ float gelu_f(float x) {
    return 0.5f * x * (1.0f + erff(x * 0.70710678118654752440f));
}

// ---------------------------------------------------------------------------
// GEMM: C[M,N] = A[M,K] @ W[N,K]^T + bias[N]   (both operands K-contiguous)
// Optional exact-GELU epilogue; optional linear-interp A source (MLP1):
//   A is then "compressed" [B=8, 64, 1024] and logical row m = b*4096 + l maps
//   to lerp(comp[b,i0,:], comp[b,i1,:], frac) per F.interpolate(linear).
// BM=BN=128, BK=16, 256 threads, 8x8 per-thread tile, double-buffered smem.
// ---------------------------------------------------------------------------
template<bool GELU, bool INTERP>
__global__ void __launch_bounds__(256) gemm_nt(
    const float* __restrict__ A, const float* __restrict__ W,
    const float* __restrict__ bias, float* __restrict__ C,
    int M, int N, int K)
{
    __shared__ __align__(16) float As[2][16][132];
    __shared__ __align__(16) float Bs[2][16][132];

    const int tid = threadIdx.x;
    const int tx  = tid & 15;
    const int ty  = tid >> 4;
    const int m0  = blockIdx.y * 128;
    const int n0  = blockIdx.x * 128;

    const int lr0 = tid >> 2;        // 0..63 (tile row for loads)
    const int lr1 = lr0 + 64;
    const int lc  = (tid & 3) << 2;  // k-offset within BK: 0,4,8,12

    // Interp source rows (only used when INTERP)
    int   ia0[2] = {0, 0}, ia1[2] = {0, 0};
    float ifr[2] = {0.f, 0.f};
    if (INTERP) {
        const int rows[2] = {m0 + lr0, m0 + lr1};
        #pragma unroll
        for (int u = 0; u < 2; u++) {
            const int b = rows[u] >> 12;
            const int l = rows[u] & 4095;
            float pos = (l + 0.5f) * 0.015625f - 0.5f;   // *(T/L) = /64
            pos = fminf(fmaxf(pos, 0.0f), 63.0f);
            const int i0 = (int)pos;                     // pos >= 0
            const int i1 = min(i0 + 1, 63);
            ifr[u] = pos - (float)i0;
            ia0[u] = (b * 64 + i0) * 1024;
            ia1[u] = (b * 64 + i1) * 1024;
        }
    }

    float acc[8][8];
    #pragma unroll
    for (int i = 0; i < 8; i++)
        #pragma unroll
        for (int j = 0; j < 8; j++) acc[i][j] = 0.0f;

    float4 ra[2], rb[2];

#define LOAD_TILE(KT)                                                          \
    {                                                                          \
        const int k0 = (KT) * 16 + lc;                                         \
        if (INTERP) {                                                          \
            _Pragma("unroll")                                                  \
            for (int u = 0; u < 2; u++) {                                      \
                const float4 c0 = *(const float4*)(A + ia0[u] + k0);           \
                const float4 c1 = *(const float4*)(A + ia1[u] + k0);           \
                const float wf1 = ifr[u], wf0 = 1.0f - wf1;                    \
                ra[u] = make_float4(c0.x*wf0 + c1.x*wf1, c0.y*wf0 + c1.y*wf1,  \
                                    c0.z*wf0 + c1.z*wf1, c0.w*wf0 + c1.w*wf1); \
            }                                                                  \
        } else {                                                               \
            int mA = m0 + lr0;                                                 \
            ra[0] = (mA < M) ? *(const float4*)(A + (size_t)mA * K + k0)       \
                             : make_float4(0.f, 0.f, 0.f, 0.f);                \
            mA = m0 + lr1;                                                     \
            ra[1] = (mA < M) ? *(const float4*)(A + (size_t)mA * K + k0)       \
                             : make_float4(0.f, 0.f, 0.f, 0.f);                \
        }                                                                      \
        rb[0] = *(const float4*)(W + (size_t)(n0 + lr0) * K + k0);             \
        rb[1] = *(const float4*)(W + (size_t)(n0 + lr1) * K + k0);             \
    }

#define STORE_TILE(BUF)                                                        \
    {                                                                          \
        As[BUF][lc+0][lr0] = ra[0].x; As[BUF][lc+1][lr0] = ra[0].y;            \
        As[BUF][lc+2][lr0] = ra[0].z; As[BUF][lc+3][lr0] = ra[0].w;            \
        As[BUF][lc+0][lr1] = ra[1].x; As[BUF][lc+1][lr1] = ra[1].y;            \
        As[BUF][lc+2][lr1] = ra[1].z; As[BUF][lc+3][lr1] = ra[1].w;            \
        Bs[BUF][lc+0][lr0] = rb[0].x; Bs[BUF][lc+1][lr0] = rb[0].y;            \
        Bs[BUF][lc+2][lr0] = rb[0].z; Bs[BUF][lc+3][lr0] = rb[0].w;            \
        Bs[BUF][lc+0][lr1] = rb[1].x; Bs[BUF][lc+1][lr1] = rb[1].y;            \
        Bs[BUF][lc+2][lr1] = rb[1].z; Bs[BUF][lc+3][lr1] = rb[1].w;            \
    }

    const int nk = K >> 4;
    LOAD_TILE(0)
    STORE_TILE(0)
    __syncthreads();

    for (int kt = 0; kt < nk; kt++) {
        const int cur = kt & 1;
        const int nxt = cur ^ 1;
        if (kt + 1 < nk) { LOAD_TILE(kt + 1) }

        #pragma unroll
        for (int kk = 0; kk < 16; kk++) {
            float af[8], bf[8];
            *(float4*)&af[0] = *(const float4*)&As[cur][kk][ty * 8];
            *(float4*)&af[4] = *(const float4*)&As[cur][kk][ty * 8 + 4];
            *(float4*)&bf[0] = *(const float4*)&Bs[cur][kk][tx * 4];
            *(float4*)&bf[4] = *(const float4*)&Bs[cur][kk][64 + tx * 4];
            #pragma unroll
            for (int i = 0; i < 8; i++)
                #pragma unroll
                for (int j = 0; j < 8; j++)
                    acc[i][j] = fmaf(af[i], bf[j], acc[i][j]);
        }

        if (kt + 1 < nk) { STORE_TILE(nxt) }
        __syncthreads();
    }

#undef LOAD_TILE
#undef STORE_TILE

    // Epilogue: bias (+ GELU), two float4 column groups per row
    const int cA = n0 + tx * 4;
    const int cB = cA + 64;
    const float4 bi0 = *(const float4*)(bias + cA);
    const float4 bi1 = *(const float4*)(bias + cB);

    #pragma unroll
    for (int i = 0; i < 8; i++) {
        const int row = m0 + ty * 8 + i;
        if (row >= M) break;
        float4 v0 = make_float4(acc[i][0] + bi0.x, acc[i][1] + bi0.y,
                                acc[i][2] + bi0.z, acc[i][3] + bi0.w);
        float4 v1 = make_float4(acc[i][4] + bi1.x, acc[i][5] + bi1.y,
                                acc[i][6] + bi1.z, acc[i][7] + bi1.w);
        if (GELU) {
            v0.x = gelu_f(v0.x); v0.y = gelu_f(v0.y);
            v0.z = gelu_f(v0.z); v0.w = gelu_f(v0.w);
            v1.x = gelu_f(v1.x); v1.y = gelu_f(v1.y);
            v1.z = gelu_f(v1.z); v1.w = gelu_f(v1.w);
        }
        *(float4*)(C + (size_t)row * N + cA) = v0;
        *(float4*)(C + (size_t)row * N + cB) = v1;
    }
}

// ---------------------------------------------------------------------------
// Attention: one CTA per (b,h). Q [64,1024] head-major, K/V [B*L,1024].
// Online softmax, 32-key tiles. Thread layout: tid = r*4 + qt
//   (r = query row 0..63, qt = quad lane). Each quad thread computes scores
//   for 8 keys and accumulates output for 16 head-dims.
// ---------------------------------------------------------------------------
__global__ void __launch_bounds__(256) attn_kernel(
    const float* __restrict__ Q,
    const float* __restrict__ Kb,
    const float* __restrict__ Vb,
    float* __restrict__ O)
{
    const int bh = blockIdx.x;
    const int b  = bh >> 4;
    const int h  = bh & 15;

    __shared__ __align__(16) float qs[64][68];
    __shared__ __align__(16) float ks[32][68];
    __shared__ __align__(16) float vs[32][68];
    __shared__ float ps[64][33];

    const int tid = threadIdx.x;
    const int r   = tid >> 2;
    const int qt  = tid & 3;

    // load Q tile for this head
    for (int i = tid; i < 64 * 16; i += 256) {
        const int row = i >> 4;
        const int c   = (i & 15) * 4;
        *(float4*)&qs[row][c] = *(const float4*)(Q + row * 1024 + h * 64 + c);
    }
    __syncthreads();

    float m = -1e30f, lsum = 0.0f;
    float4 o[4];
    #pragma unroll
    for (int c = 0; c < 4; c++) o[c] = make_float4(0.f, 0.f, 0.f, 0.f);

    const size_t base = (size_t)b * 4096 * 1024 + h * 64;

    for (int t0 = 0; t0 < 4096; t0 += 32) {
        // load K/V tiles (32 rows x 64 dims each)
        for (int i = tid; i < 32 * 16; i += 256) {
            const int row = i >> 4;
            const int c   = (i & 15) * 4;
            const size_t g = base + (size_t)(t0 + row) * 1024 + c;
            *(float4*)&ks[row][c] = *(const float4*)(Kb + g);
            *(float4*)&vs[row][c] = *(const float4*)(Vb + g);
        }
        __syncthreads();

        // scores for this thread's 8 keys
        float s[8];
        #pragma unroll
        for (int jj = 0; jj < 8; jj++) s[jj] = 0.0f;
        #pragma unroll
        for (int d = 0; d < 64; d += 4) {
            const float4 q4 = *(const float4*)&qs[r][d];
            #pragma unroll
            for (int jj = 0; jj < 8; jj++) {
                const float4 k4 = *(const float4*)&ks[qt * 8 + jj][d];
                s[jj] = fmaf(q4.x, k4.x, s[jj]);
                s[jj] = fmaf(q4.y, k4.y, s[jj]);
                s[jj] = fmaf(q4.z, k4.z, s[jj]);
                s[jj] = fmaf(q4.w, k4.w, s[jj]);
            }
        }
        float tmax = -1e30f;
        #pragma unroll
        for (int jj = 0; jj < 8; jj++) { s[jj] *= 0.125f; tmax = fmaxf(tmax, s[jj]); }
        tmax = fmaxf(tmax, __shfl_xor_sync(0xffffffffu, tmax, 1));
        tmax = fmaxf(tmax, __shfl_xor_sync(0xffffffffu, tmax, 2));

        const float mnew  = fmaxf(m, tmax);
        const float alpha = expf(m - mnew);
        float psum = 0.0f;
        #pragma unroll
        for (int jj = 0; jj < 8; jj++) {
            const float p = expf(s[jj] - mnew);
            ps[r][qt * 8 + jj] = p;
            psum += p;
        }
        psum += __shfl_xor_sync(0xffffffffu, psum, 1);
        psum += __shfl_xor_sync(0xffffffffu, psum, 2);
        lsum = lsum * alpha + psum;
        m = mnew;
        #pragma unroll
        for (int c = 0; c < 4; c++) {
            o[c].x *= alpha; o[c].y *= alpha; o[c].z *= alpha; o[c].w *= alpha;
        }
        __syncwarp();

        // accumulate P @ V for this thread's 16 dims
        #pragma unroll
        for (int j = 0; j < 32; j++) {
            const float p = ps[r][j];
            #pragma unroll
            for (int c = 0; c < 4; c++) {
                const float4 v4 = *(const float4*)&vs[j][qt * 16 + c * 4];
                o[c].x = fmaf(p, v4.x, o[c].x);
                o[c].y = fmaf(p, v4.y, o[c].y);
                o[c].z = fmaf(p, v4.z, o[c].z);
                o[c].w = fmaf(p, v4.w, o[c].w);
            }
        }
        __syncthreads();
    }

    const float inv = 1.0f / lsum;
    float* op = O + (size_t)(b * 64 + r) * 1024 + h * 64 + qt * 16;
    #pragma unroll
    for (int c = 0; c < 4; c++) {
        o[c].x *= inv; o[c].y *= inv; o[c].z *= inv; o[c].w *= inv;
        *(float4*)(op + c * 4) = o[c];
    }
}

// ---------------------------------------------------------------------------
// LayerNorm over D=1024, one CTA per row of [512, 1024]
// ---------------------------------------------------------------------------
__global__ void __launch_bounds__(256) ln_kernel(
    const float* __restrict__ X, const float* __restrict__ g,
    const float* __restrict__ be, float* __restrict__ Y)
{
    const int row = blockIdx.x;
    const int tid = threadIdx.x;
    __shared__ float red[256];

    float v[4];
    #pragma unroll
    for (int i = 0; i < 4; i++) v[i] = X[(size_t)row * 1024 + tid + i * 256];

    float s = v[0] + v[1] + v[2] + v[3];
    red[tid] = s;
    __syncthreads();
    for (int st = 128; st > 0; st >>= 1) {
        if (tid < st) red[tid] += red[tid + st];
        __syncthreads();
    }
    const float mean = red[0] * (1.0f / 1024.0f);
    __syncthreads();

    float q = 0.0f;
    #pragma unroll
    for (int i = 0; i < 4; i++) { const float d = v[i] - mean; q = fmaf(d, d, q); }
    red[tid] = q;
    __syncthreads();
    for (int st = 128; st > 0; st >>= 1) {
        if (tid < st) red[tid] += red[tid + st];
        __syncthreads();
    }
    const float var  = red[0] * (1.0f / 1024.0f);
    const float rstd = rsqrtf(var + 1e-5f);

    #pragma unroll
    for (int i = 0; i < 4; i++) {
        const int c = tid + i * 256;
        Y[(size_t)row * 1024 + c] = (v[i] - mean) * rstd * g[c] + be[c];
    }
}

// ---------------------------------------------------------------------------
// Launch
// ---------------------------------------------------------------------------
extern "C" void kernel_launch(void* const* d_in, const int* in_sizes, int n_in,
                              void* d_out, int out_size)
{
    const float* memory = (const float*)d_in[0];   // [8,4096,1024]
    const float* query  = (const float*)d_in[1];   // [1,64,1024]
    const float* ipw    = (const float*)d_in[2];   // [3072,1024]
    const float* ipb    = (const float*)d_in[3];   // [3072]
    const float* opw    = (const float*)d_in[4];   // [1024,1024]
    const float* opb    = (const float*)d_in[5];   // [1024]
    const float* lng    = (const float*)d_in[6];   // [1024]
    const float* lnb    = (const float*)d_in[7];   // [1024]
    const float* w1     = (const float*)d_in[8];   // [2048,1024]
    const float* b1     = (const float*)d_in[9];   // [2048]
    const float* w2     = (const float*)d_in[10];  // [1024,2048]
    const float* b2     = (const float*)d_in[11];  // [1024]

    float* out   = (float*)d_out;
    float* comp  = out;              // [8*64,1024] = 524288 floats
    float* recon = out + 524288;     // [8*4096,1024]

    void* sp = nullptr;
    cudaGetSymbolAddress(&sp, g_scratch);
    float* S    = (float*)sp;
    float* Kbuf = S;
    float* Vbuf = S + 33554432;
    float* Qbuf = S + 67108864;
    float* Abuf = Qbuf + 65536;
    float* Obuf = Abuf + 524288;
    float* Hbuf = S;                 // reuses K/V after attention

    const dim3 th(256);

    // Q projection: [64,1024] = query @ Wq^T + bq
    gemm_nt<false, false><<<dim3(8, 1), th>>>(query, ipw, ipb, Qbuf, 64, 1024, 1024);
    // K projection: [32768,1024]
    gemm_nt<false, false><<<dim3(8, 256), th>>>(memory, ipw + 1048576, ipb + 1024,
                                                Kbuf, 32768, 1024, 1024);
    // V projection
    gemm_nt<false, false><<<dim3(8, 256), th>>>(memory, ipw + 2097152, ipb + 2048,
                                                Vbuf, 32768, 1024, 1024);
    // Attention per (b,h)
    attn_kernel<<<128, th>>>(Qbuf, Kbuf, Vbuf, Abuf);
    // Output projection: [512,1024]
    gemm_nt<false, false><<<dim3(8, 4), th>>>(Abuf, opw, opb, Obuf, 512, 1024, 1024);
    // LayerNorm -> compressed (first output)
    ln_kernel<<<512, th>>>(Obuf, lng, lnb, comp);
    // MLP1 with fused linear interpolation of compressed + exact GELU
    gemm_nt<true, true><<<dim3(16, 256), th>>>(comp, w1, b1, Hbuf, 32768, 2048, 1024);
    // MLP2 -> recon (second output)
    gemm_nt<false, false><<<dim3(8, 256), th>>>(Hbuf, w2, b2, recon, 32768, 1024, 2048);
}

// round 3
// speedup vs baseline: 1.9128x; 1.9128x over previous
#include <cuda_runtime.h>
#include <math.h>

// Problem constants: B=8, L=4096, D=1024, H=16, T=64, hd=64

// Scratch arena layout (floats):
//   [0,        33554432)  K proj   [32768,1024]   (reused as H [32768,2048] later)
//   [33554432, 67108864)  V proj   [32768,1024]
//   [67108864, 67174400)  Q proj   [64,1024]
//   [67174400, 67698688)  attn out [512,1024]
//   [67698688, 68222976)  out-proj [512,1024]
__device__ float g_scratch[68222976];

__device__ __forceinline__ float gelu_f(float x) {
    return 0.5f * x * (1.0f + erff(x * 0.70710678118654752440f));
}

__device__ __forceinline__ unsigned to_tf32(float x) {
    unsigned r;
    asm("cvt.rna.tf32.f32 %0, %1;" : "=r"(r) : "f"(x));
    return r;
}

// ---------------------------------------------------------------------------
// TF32 tensor-core GEMM: C[M,N] = A[M,K] @ W[N,K]^T + bias[N]
// mma.sync.aligned.m16n8k8.row.col.f32.tf32.tf32.f32
// CTA tile 128x128xBK16, 256 threads = 8 warps in 4(m) x 2(n) grid,
// warp tile 32x64 = 2 m16-tiles x 8 n8-tiles. Double-buffered smem.
// Optional exact-GELU epilogue; optional linear-interp A source (MLP1):
//   logical row m = b*4096 + l reads lerp of compressed[b, i0/i1, :].
// ---------------------------------------------------------------------------
template<bool GELU, bool INTERP>
__global__ void __launch_bounds__(256) gemm_tf32(
    const float* __restrict__ A, const float* __restrict__ W,
    const float* __restrict__ bias, float* __restrict__ C,
    int M, int N, int K)
{
    // [buf][k][m or n], stride 132: bank = (4k + x) % 32 -> conflict-free frags
    __shared__ unsigned As[2][16][132];
    __shared__ unsigned Bs[2][16][132];

    const int tid  = threadIdx.x;
    const int warp = tid >> 5;
    const int lane = tid & 31;
    const int wm   = warp & 3;       // 0..3
    const int wn   = warp >> 2;      // 0..1
    const int gr   = lane >> 2;      // 0..7
    const int tg   = lane & 3;       // 0..3

    const int m0 = blockIdx.y * 128;
    const int n0 = blockIdx.x * 128;

    // loader indexing
    const int lr0 = tid >> 2;        // 0..63
    const int lr1 = lr0 + 64;
    const int lc  = (tid & 3) << 2;  // 0,4,8,12

    // Interp source rows (MLP1 only)
    int   ia0[2] = {0, 0}, ia1[2] = {0, 0};
    float ifr[2] = {0.f, 0.f};
    if (INTERP) {
        const int rows[2] = {m0 + lr0, m0 + lr1};
        #pragma unroll
        for (int u = 0; u < 2; u++) {
            const int b = rows[u] >> 12;
            const int l = rows[u] & 4095;
            float pos = (l + 0.5f) * 0.015625f - 0.5f;
            pos = fminf(fmaxf(pos, 0.0f), 63.0f);
            const int i0 = (int)pos;
            const int i1 = min(i0 + 1, 63);
            ifr[u] = pos - (float)i0;
            ia0[u] = (b * 64 + i0) * 1024;
            ia1[u] = (b * 64 + i1) * 1024;
        }
    }

    float acc[2][8][4];
    #pragma unroll
    for (int mt = 0; mt < 2; mt++)
        #pragma unroll
        for (int nt = 0; nt < 8; nt++)
            #pragma unroll
            for (int r = 0; r < 4; r++) acc[mt][nt][r] = 0.0f;

    float4 ra[2], rb[2];

#define LOAD_TILE(KT)                                                          \
    {                                                                          \
        const int k0 = (KT) * 16 + lc;                                         \
        if (INTERP) {                                                          \
            _Pragma("unroll")                                                  \
            for (int u = 0; u < 2; u++) {                                      \
                const float4 c0 = *(const float4*)(A + ia0[u] + k0);           \
                const float4 c1 = *(const float4*)(A + ia1[u] + k0);           \
                const float wf1 = ifr[u], wf0 = 1.0f - wf1;                    \
                ra[u] = make_float4(c0.x*wf0 + c1.x*wf1, c0.y*wf0 + c1.y*wf1,  \
                                    c0.z*wf0 + c1.z*wf1, c0.w*wf0 + c1.w*wf1); \
            }                                                                  \
        } else {                                                               \
            int mA = m0 + lr0;                                                 \
            ra[0] = (mA < M) ? *(const float4*)(A + (size_t)mA * K + k0)       \
                             : make_float4(0.f, 0.f, 0.f, 0.f);                \
            mA = m0 + lr1;                                                     \
            ra[1] = (mA < M) ? *(const float4*)(A + (size_t)mA * K + k0)       \
                             : make_float4(0.f, 0.f, 0.f, 0.f);                \
        }                                                                      \
        rb[0] = *(const float4*)(W + (size_t)(n0 + lr0) * K + k0);             \
        rb[1] = *(const float4*)(W + (size_t)(n0 + lr1) * K + k0);             \
    }

#define STORE_TILE(BUF)                                                        \
    {                                                                          \
        As[BUF][lc+0][lr0] = to_tf32(ra[0].x);                                 \
        As[BUF][lc+1][lr0] = to_tf32(ra[0].y);                                 \
        As[BUF][lc+2][lr0] = to_tf32(ra[0].z);                                 \
        As[BUF][lc+3][lr0] = to_tf32(ra[0].w);                                 \
        As[BUF][lc+0][lr1] = to_tf32(ra[1].x);                                 \
        As[BUF][lc+1][lr1] = to_tf32(ra[1].y);                                 \
        As[BUF][lc+2][lr1] = to_tf32(ra[1].z);                                 \
        As[BUF][lc+3][lr1] = to_tf32(ra[1].w);                                 \
        Bs[BUF][lc+0][lr0] = to_tf32(rb[0].x);                                 \
        Bs[BUF][lc+1][lr0] = to_tf32(rb[0].y);                                 \
        Bs[BUF][lc+2][lr0] = to_tf32(rb[0].z);                                 \
        Bs[BUF][lc+3][lr0] = to_tf32(rb[0].w);                                 \
        Bs[BUF][lc+0][lr1] = to_tf32(rb[1].x);                                 \
        Bs[BUF][lc+1][lr1] = to_tf32(rb[1].y);                                 \
        Bs[BUF][lc+2][lr1] = to_tf32(rb[1].z);                                 \
        Bs[BUF][lc+3][lr1] = to_tf32(rb[1].w);                                 \
    }

    const int nk = K >> 4;
    LOAD_TILE(0)
    STORE_TILE(0)
    __syncthreads();

    const int mrow0 = wm * 32 + gr;   // + mt*16 (+8 for a1/a3)
    const int ncol0 = wn * 64 + gr;   // + nt*8

    for (int kt = 0; kt < nk; kt++) {
        const int cur = kt & 1;
        const int nxt = cur ^ 1;
        if (kt + 1 < nk) { LOAD_TILE(kt + 1) }

        #pragma unroll
        for (int ks = 0; ks < 2; ks++) {
            const int kA = ks * 8 + tg;      // rows kA and kA+4 of the k-slab
            unsigned a[2][4], b[8][2];
            #pragma unroll
            for (int mt = 0; mt < 2; mt++) {
                const int m = mrow0 + mt * 16;
                a[mt][0] = As[cur][kA    ][m];
                a[mt][1] = As[cur][kA    ][m + 8];
                a[mt][2] = As[cur][kA + 4][m];
                a[mt][3] = As[cur][kA + 4][m + 8];
            }
            #pragma unroll
            for (int nt = 0; nt < 8; nt++) {
                const int n = ncol0 + nt * 8;
                b[nt][0] = Bs[cur][kA    ][n];
                b[nt][1] = Bs[cur][kA + 4][n];
            }
            #pragma unroll
            for (int mt = 0; mt < 2; mt++)
                #pragma unroll
                for (int nt = 0; nt < 8; nt++) {
                    asm volatile(
                        "mma.sync.aligned.m16n8k8.row.col.f32.tf32.tf32.f32 "
                        "{%0,%1,%2,%3}, {%4,%5,%6,%7}, {%8,%9}, {%0,%1,%2,%3};"
                        : "+f"(acc[mt][nt][0]), "+f"(acc[mt][nt][1]),
                          "+f"(acc[mt][nt][2]), "+f"(acc[mt][nt][3])
                        : "r"(a[mt][0]), "r"(a[mt][1]), "r"(a[mt][2]), "r"(a[mt][3]),
                          "r"(b[nt][0]), "r"(b[nt][1]));
                }
        }

        if (kt + 1 < nk) { STORE_TILE(nxt) }
        __syncthreads();
    }

#undef LOAD_TILE
#undef STORE_TILE

    // Epilogue: bias (+GELU), float2 stores per C fragment pair
    #pragma unroll
    for (int nt = 0; nt < 8; nt++) {
        const int cn = n0 + wn * 64 + nt * 8 + tg * 2;
        const float b0 = __ldg(bias + cn);
        const float b1 = __ldg(bias + cn + 1);
        #pragma unroll
        for (int mt = 0; mt < 2; mt++) {
            const int r0 = m0 + wm * 32 + mt * 16 + gr;
            const int r1 = r0 + 8;
            float v0 = acc[mt][nt][0] + b0, v1 = acc[mt][nt][1] + b1;
            float v2 = acc[mt][nt][2] + b0, v3 = acc[mt][nt][3] + b1;
            if (GELU) {
                v0 = gelu_f(v0); v1 = gelu_f(v1);
                v2 = gelu_f(v2); v3 = gelu_f(v3);
            }
            if (r0 < M) *(float2*)(C + (size_t)r0 * N + cn) = make_float2(v0, v1);
            if (r1 < M) *(float2*)(C + (size_t)r1 * N + cn) = make_float2(v2, v3);
        }
    }
}

// ---------------------------------------------------------------------------
// Attention: one CTA per (b,h). Online softmax over 32-key tiles. fp32 SIMT.
// ---------------------------------------------------------------------------
__global__ void __launch_bounds__(256) attn_kernel(
    const float* __restrict__ Q,
    const float* __restrict__ Kb,
    const float* __restrict__ Vb,
    float* __restrict__ O)
{
    const int bh = blockIdx.x;
    const int b  = bh >> 4;
    const int h  = bh & 15;

    __shared__ __align__(16) float qs[64][68];
    __shared__ __align__(16) float ks[32][68];
    __shared__ __align__(16) float vs[32][68];
    __shared__ float ps[64][33];

    const int tid = threadIdx.x;
    const int r   = tid >> 2;
    const int qt  = tid & 3;

    for (int i = tid; i < 64 * 16; i += 256) {
        const int row = i >> 4;
        const int c   = (i & 15) * 4;
        *(float4*)&qs[row][c] = *(const float4*)(Q + row * 1024 + h * 64 + c);
    }
    __syncthreads();

    float m = -1e30f, lsum = 0.0f;
    float4 o[4];
    #pragma unroll
    for (int c = 0; c < 4; c++) o[c] = make_float4(0.f, 0.f, 0.f, 0.f);

    const size_t base = (size_t)b * 4096 * 1024 + h * 64;

    for (int t0 = 0; t0 < 4096; t0 += 32) {
        for (int i = tid; i < 32 * 16; i += 256) {
            const int row = i >> 4;
            const int c   = (i & 15) * 4;
            const size_t g = base + (size_t)(t0 + row) * 1024 + c;
            *(float4*)&ks[row][c] = *(const float4*)(Kb + g);
            *(float4*)&vs[row][c] = *(const float4*)(Vb + g);
        }
        __syncthreads();

        float s[8];
        #pragma unroll
        for (int jj = 0; jj < 8; jj++) s[jj] = 0.0f;
        #pragma unroll
        for (int d = 0; d < 64; d += 4) {
            const float4 q4 = *(const float4*)&qs[r][d];
            #pragma unroll
            for (int jj = 0; jj < 8; jj++) {
                const float4 k4 = *(const float4*)&ks[qt * 8 + jj][d];
                s[jj] = fmaf(q4.x, k4.x, s[jj]);
                s[jj] = fmaf(q4.y, k4.y, s[jj]);
                s[jj] = fmaf(q4.z, k4.z, s[jj]);
                s[jj] = fmaf(q4.w, k4.w, s[jj]);
            }
        }
        float tmax = -1e30f;
        #pragma unroll
        for (int jj = 0; jj < 8; jj++) { s[jj] *= 0.125f; tmax = fmaxf(tmax, s[jj]); }
        tmax = fmaxf(tmax, __shfl_xor_sync(0xffffffffu, tmax, 1));
        tmax = fmaxf(tmax, __shfl_xor_sync(0xffffffffu, tmax, 2));

        const float mnew  = fmaxf(m, tmax);
        const float alpha = expf(m - mnew);
        float psum = 0.0f;
        #pragma unroll
        for (int jj = 0; jj < 8; jj++) {
            const float p = expf(s[jj] - mnew);
            ps[r][qt * 8 + jj] = p;
            psum += p;
        }
        psum += __shfl_xor_sync(0xffffffffu, psum, 1);
        psum += __shfl_xor_sync(0xffffffffu, psum, 2);
        lsum = lsum * alpha + psum;
        m = mnew;
        #pragma unroll
        for (int c = 0; c < 4; c++) {
            o[c].x *= alpha; o[c].y *= alpha; o[c].z *= alpha; o[c].w *= alpha;
        }
        __syncwarp();

        #pragma unroll
        for (int j = 0; j < 32; j++) {
            const float p = ps[r][j];
            #pragma unroll
            for (int c = 0; c < 4; c++) {
                const float4 v4 = *(const float4*)&vs[j][qt * 16 + c * 4];
                o[c].x = fmaf(p, v4.x, o[c].x);
                o[c].y = fmaf(p, v4.y, o[c].y);
                o[c].z = fmaf(p, v4.z, o[c].z);
                o[c].w = fmaf(p, v4.w, o[c].w);
            }
        }
        __syncthreads();
    }

    const float inv = 1.0f / lsum;
    float* op = O + (size_t)(b * 64 + r) * 1024 + h * 64 + qt * 16;
    #pragma unroll
    for (int c = 0; c < 4; c++) {
        o[c].x *= inv; o[c].y *= inv; o[c].z *= inv; o[c].w *= inv;
        *(float4*)(op + c * 4) = o[c];
    }
}

// ---------------------------------------------------------------------------
// LayerNorm over D=1024, one CTA per row of [512, 1024]
// ---------------------------------------------------------------------------
__global__ void __launch_bounds__(256) ln_kernel(
    const float* __restrict__ X, const float* __restrict__ g,
    const float* __restrict__ be, float* __restrict__ Y)
{
    const int row = blockIdx.x;
    const int tid = threadIdx.x;
    __shared__ float red[256];

    float v[4];
    #pragma unroll
    for (int i = 0; i < 4; i++) v[i] = X[(size_t)row * 1024 + tid + i * 256];

    float s = v[0] + v[1] + v[2] + v[3];
    red[tid] = s;
    __syncthreads();
    for (int st = 128; st > 0; st >>= 1) {
        if (tid < st) red[tid] += red[tid + st];
        __syncthreads();
    }
    const float mean = red[0] * (1.0f / 1024.0f);
    __syncthreads();

    float q = 0.0f;
    #pragma unroll
    for (int i = 0; i < 4; i++) { const float d = v[i] - mean; q = fmaf(d, d, q); }
    red[tid] = q;
    __syncthreads();
    for (int st = 128; st > 0; st >>= 1) {
        if (tid < st) red[tid] += red[tid + st];
        __syncthreads();
    }
    const float var  = red[0] * (1.0f / 1024.0f);
    const float rstd = rsqrtf(var + 1e-5f);

    #pragma unroll
    for (int i = 0; i < 4; i++) {
        const int c = tid + i * 256;
        Y[(size_t)row * 1024 + c] = (v[i] - mean) * rstd * g[c] + be[c];
    }
}

// ---------------------------------------------------------------------------
// Launch
// ---------------------------------------------------------------------------
extern "C" void kernel_launch(void* const* d_in, const int* in_sizes, int n_in,
                              void* d_out, int out_size)
{
    const float* memory = (const float*)d_in[0];   // [8,4096,1024]
    const float* query  = (const float*)d_in[1];   // [1,64,1024]
    const float* ipw    = (const float*)d_in[2];   // [3072,1024]
    const float* ipb    = (const float*)d_in[3];   // [3072]
    const float* opw    = (const float*)d_in[4];   // [1024,1024]
    const float* opb    = (const float*)d_in[5];   // [1024]
    const float* lng    = (const float*)d_in[6];   // [1024]
    const float* lnb    = (const float*)d_in[7];   // [1024]
    const float* w1     = (const float*)d_in[8];   // [2048,1024]
    const float* b1     = (const float*)d_in[9];   // [2048]
    const float* w2     = (const float*)d_in[10];  // [1024,2048]
    const float* b2     = (const float*)d_in[11];  // [1024]

    float* out   = (float*)d_out;
    float* comp  = out;              // [512,1024]
    float* recon = out + 524288;     // [32768,1024]

    void* sp = nullptr;
    cudaGetSymbolAddress(&sp, g_scratch);
    float* S    = (float*)sp;
    float* Kbuf = S;
    float* Vbuf = S + 33554432;
    float* Qbuf = S + 67108864;
    float* Abuf = Qbuf + 65536;
    float* Obuf = Abuf + 524288;
    float* Hbuf = S;                 // reuses K/V after attention

    const dim3 th(256);

    // Q projection [64,1024]
    gemm_tf32<false, false><<<dim3(8, 1), th>>>(query, ipw, ipb, Qbuf, 64, 1024, 1024);
    // K projection [32768,1024]
    gemm_tf32<false, false><<<dim3(8, 256), th>>>(memory, ipw + 1048576, ipb + 1024,
                                                  Kbuf, 32768, 1024, 1024);
    // V projection [32768,1024]
    gemm_tf32<false, false><<<dim3(8, 256), th>>>(memory, ipw + 2097152, ipb + 2048,
                                                  Vbuf, 32768, 1024, 1024);
    // Attention per (b,h)
    attn_kernel<<<128, th>>>(Qbuf, Kbuf, Vbuf, Abuf);
    // Output projection [512,1024]
    gemm_tf32<false, false><<<dim3(8, 4), th>>>(Abuf, opw, opb, Obuf, 512, 1024, 1024);
    // LayerNorm -> compressed (first output)
    ln_kernel<<<512, th>>>(Obuf, lng, lnb, comp);
    // MLP1: fused interpolation + exact GELU, [32768,2048]
    gemm_tf32<true, true><<<dim3(16, 256), th>>>(comp, w1, b1, Hbuf, 32768, 2048, 1024);
    // MLP2 -> recon [32768,1024]
    gemm_tf32<false, false><<<dim3(8, 256), th>>>(Hbuf, w2, b2, recon, 32768, 1024, 2048);
}